// round 4
// baseline (speedup 1.0000x reference)
#include <cuda_runtime.h>
#include <cuda_bf16.h>
#include <cstdint>

// Problem constants (fixed by the dataset)
#define NN 100000
#define NE 1600000
#define DD 64
#define CH 128                        // scan chunk size

// ---------------- device scratch (no allocations allowed) ----------------
// Referenced ONLY inside device code; kernel_launch passes only harness
// pointers + scalars (device-symbol host args fault with 717).
__device__ __align__(256) int   g_deg[NN];
__device__ __align__(256) float g_dinv[NN];
__device__ __align__(256) int   g_rowptr[NN + 1];
__device__ __align__(256) int   g_cursor[NN];
__device__ __align__(256) int   g_csums[1024];
__device__ __align__(256) int   g_csr[NE];
__device__ __align__(256) float g_hn[(size_t)NN * DD];   // (x@W)*dinv[row]
__device__ __align__(256) float g_h1[(size_t)NN * DD];   // layer-1 output

// ---------------- graph preprocessing ----------------
// NOTE: edge_index is int32 on device (JAX x64 disabled demotes jnp.int64).

__global__ void k_init(int n) {
    int i = blockIdx.x * blockDim.x + threadIdx.x;
    if (i < n) g_deg[i] = 0;
}

__global__ void k_hist(const int* __restrict__ dst, int e, int n) {
    int i = blockIdx.x * blockDim.x + threadIdx.x;
    if (i >= e) return;
    int d = dst[i];
    if ((unsigned)d < (unsigned)n)            // defensive: crash -> diagnosable
        atomicAdd(&g_deg[d], 1);
}

__global__ void k_dinv(int n) {
    int i = blockIdx.x * blockDim.x + threadIdx.x;
    if (i < n) g_dinv[i] = rsqrtf((float)(g_deg[i] + 1));   // +1 self-loop
}

// chunked exclusive scan: pass1 per-chunk sums
__global__ void k_scan1(int n, int nch) {
    int t = blockIdx.x * blockDim.x + threadIdx.x;
    if (t >= nch) return;
    int base = t * CH;
    int end = min(base + CH, n);
    int s = 0;
    for (int i = base; i < end; i++) s += g_deg[i];
    g_csums[t] = s;
}

// pass2: single-block exclusive scan of chunk sums (nch <= 1024)
__global__ void k_scan2(int nch) {
    __shared__ int sh[1024];
    int t = threadIdx.x;
    int v = (t < nch) ? g_csums[t] : 0;
    sh[t] = v;
    __syncthreads();
    for (int off = 1; off < 1024; off <<= 1) {
        int add = (t >= off) ? sh[t - off] : 0;
        __syncthreads();
        sh[t] += add;
        __syncthreads();
    }
    if (t < nch) g_csums[t] = sh[t] - v;   // exclusive
}

// pass3: per-chunk rewalk -> rowptr + cursor copy
__global__ void k_scan3(int n, int nch, int e) {
    int t = blockIdx.x * blockDim.x + threadIdx.x;
    if (t >= nch) return;
    int base = t * CH;
    int end = min(base + CH, n);
    int run = g_csums[t];
    for (int i = base; i < end; i++) {
        g_rowptr[i] = run;
        g_cursor[i] = run;
        run += g_deg[i];
    }
    if (t == 0) g_rowptr[n] = e;
}

__global__ void k_scatter(const int* __restrict__ src,
                          const int* __restrict__ dst, int e, int n) {
    int i = blockIdx.x * blockDim.x + threadIdx.x;
    if (i >= e) return;
    int d = dst[i];
    int s = src[i];
    if ((unsigned)d >= (unsigned)n || (unsigned)s >= (unsigned)n) return;
    int pos = atomicAdd(&g_cursor[d], 1);
    if ((unsigned)pos < (unsigned)NE) g_csr[pos] = s;
}

// ---------------- GEMM: g_hn[row] = (x[row] @ W) * dinv[row] ----------------
// layer==0: x = emb (harness ptr). layer==1: x = g_h1 (device global).
// One thread per row; W staged in shared as float4 (broadcast LDS).
__global__ void __launch_bounds__(128) k_gemm(
    const float* __restrict__ emb, const float* __restrict__ W,
    int layer, int n) {
    __shared__ float4 Ws[64 * 16];
    for (int t = threadIdx.x; t < 1024; t += blockDim.x)
        Ws[t] = reinterpret_cast<const float4*>(W)[t];
    __syncthreads();
    int row = blockIdx.x * blockDim.x + threadIdx.x;
    if (row >= n) return;
    const float* x = (layer == 0) ? emb : g_h1;
    const float* xr = x + (size_t)row * DD;
    float4 acc[16];
#pragma unroll
    for (int j = 0; j < 16; j++) acc[j] = make_float4(0.f, 0.f, 0.f, 0.f);
#pragma unroll 4
    for (int k = 0; k < 64; k++) {
        float xv = xr[k];
#pragma unroll
        for (int j = 0; j < 16; j++) {
            float4 w = Ws[k * 16 + j];
            acc[j].x = fmaf(xv, w.x, acc[j].x);
            acc[j].y = fmaf(xv, w.y, acc[j].y);
            acc[j].z = fmaf(xv, w.z, acc[j].z);
            acc[j].w = fmaf(xv, w.w, acc[j].w);
        }
    }
    float di = g_dinv[row];
    float4* op = reinterpret_cast<float4*>(g_hn + (size_t)row * DD);
#pragma unroll
    for (int j = 0; j < 16; j++) {
        acc[j].x *= di; acc[j].y *= di; acc[j].z *= di; acc[j].w *= di;
        op[j] = acc[j];
    }
}

// ---- aggregation: out = relu(dinv[i]*(g_hn[i] + sum_nbr g_hn[s]) + b) ----
// layer==0 writes g_h1; layer==1 writes d_out (harness ptr).
// 64 threads per node (thread owns one column); 256B coalesced gathers.
__global__ void __launch_bounds__(256) k_agg(
    const float* __restrict__ b, float* __restrict__ dout,
    int layer, int n) {
    int tid = blockIdx.x * blockDim.x + threadIdx.x;
    int node = tid >> 6;
    int j = tid & 63;
    if (node >= n) return;
    float* out = (layer == 0) ? g_h1 : dout;
    int p = g_rowptr[node];
    int end = g_rowptr[node + 1];
    float acc0 = g_hn[(size_t)node * DD + j];   // self-loop term
    float acc1 = 0.f;
    // 2-way unrolled for MLP (independent gathers in flight)
    for (; p + 2 <= end; p += 2) {
        int s0 = g_csr[p];
        int s1 = g_csr[p + 1];
        acc0 += g_hn[(size_t)s0 * DD + j];
        acc1 += g_hn[(size_t)s1 * DD + j];
    }
    if (p < end) {
        int s = g_csr[p];
        acc0 += g_hn[(size_t)s * DD + j];
    }
    float v = (acc0 + acc1) * g_dinv[node] + b[j];
    out[(size_t)node * DD + j] = fmaxf(v, 0.f);
}

// ---------------- launch (ONLY kernel launches — nothing else) ----------------
extern "C" void kernel_launch(void* const* d_in, const int* in_sizes, int n_in,
                              void* d_out, int out_size) {
    const float* emb = (const float*)d_in[0];
    const int*   ei  = (const int*)d_in[1];     // int32 (JAX x64 disabled)
    const float* W1  = (const float*)d_in[2];
    const float* b1  = (const float*)d_in[3];
    const float* W2  = (const float*)d_in[4];
    const float* b2  = (const float*)d_in[5];
    float*       out = (float*)d_out;

    int N = in_sizes[0] / DD;
    int E = in_sizes[1] / 2;
    const int* srcp = ei;       // edge_index[0]
    const int* dstp = ei + E;   // edge_index[1]
    int nch = (N + CH - 1) / CH;

    // graph preprocessing (per launch — deterministic work)
    k_init<<<(N + 255) / 256, 256>>>(N);
    k_hist<<<(E + 255) / 256, 256>>>(dstp, E, N);
    k_dinv<<<(N + 255) / 256, 256>>>(N);
    k_scan1<<<(nch + 127) / 128, 128>>>(N, nch);
    k_scan2<<<1, 1024>>>(nch);
    k_scan3<<<(nch + 127) / 128, 128>>>(N, nch, E);
    k_scatter<<<(E + 255) / 256, 256>>>(srcp, dstp, E, N);

    // layer 1: g_hn = (emb @ W1)*dinv ; g_h1 = relu(dinv*sum + b1)
    k_gemm<<<(N + 127) / 128, 128>>>(emb, W1, 0, N);
    k_agg<<<(N * DD + 255) / 256, 256>>>(b1, out, 0, N);
    // layer 2: g_hn = (g_h1 @ W2)*dinv ; out = relu(dinv*sum + b2)
    k_gemm<<<(N + 127) / 128, 128>>>(emb, W2, 1, N);
    k_agg<<<(N * DD + 255) / 256, 256>>>(b2, out, 1, N);
}

// round 5
// speedup vs baseline: 1.3607x; 1.3607x over previous
#include <cuda_runtime.h>
#include <cuda_fp16.h>
#include <cstdint>

// Problem constants (fixed by the dataset)
#define NN 100000
#define NE 1600000
#define DD 64
#define CH 128                        // scan chunk size

// ---------------- device scratch (no allocations allowed) ----------------
// Referenced ONLY inside device code; kernel_launch passes only harness
// pointers + scalars (device-symbol host args fault with 717).
__device__ __align__(256) int     g_deg[NN];
__device__ __align__(256) float   g_dinv[NN];
__device__ __align__(256) int     g_rowptr[NN + 1];
__device__ __align__(256) int     g_cursor[NN];
__device__ __align__(256) int     g_csums[1024];
__device__ __align__(256) int     g_csr[NE];
__device__ __align__(256) __half2 g_hn[(size_t)NN * 32];  // (x@W)*dinv, fp16
__device__ __align__(256) float   g_h1[(size_t)NN * DD];  // layer-1 output

// ---------------- graph preprocessing (edge_index is int32) ----------------

__global__ void k_init(int n) {
    int i = blockIdx.x * blockDim.x + threadIdx.x;
    if (i < n) g_deg[i] = 0;
}

__global__ void k_hist(const int* __restrict__ dst, int e, int n) {
    int i = blockIdx.x * blockDim.x + threadIdx.x;
    if (i >= e) return;
    int d = dst[i];
    if ((unsigned)d < (unsigned)n) atomicAdd(&g_deg[d], 1);
}

// per-chunk sums: one block per chunk, warp-shuffle reduce (was serial loop)
__global__ void k_scan1(int n) {
    int b = blockIdx.x, t = threadIdx.x;
    int i = b * CH + t;
    int v = (i < n) ? g_deg[i] : 0;
#pragma unroll
    for (int o = 16; o; o >>= 1) v += __shfl_down_sync(0xFFFFFFFFu, v, o);
    __shared__ int ws[4];
    if ((t & 31) == 0) ws[t >> 5] = v;
    __syncthreads();
    if (t == 0) g_csums[b] = ws[0] + ws[1] + ws[2] + ws[3];
}

// single-block exclusive scan of chunk sums (nch <= 1024)
__global__ void k_scan2(int nch) {
    __shared__ int sh[1024];
    int t = threadIdx.x;
    int v = (t < nch) ? g_csums[t] : 0;
    sh[t] = v;
    __syncthreads();
    for (int off = 1; off < 1024; off <<= 1) {
        int add = (t >= off) ? sh[t - off] : 0;
        __syncthreads();
        sh[t] += add;
        __syncthreads();
    }
    if (t < nch) g_csums[t] = sh[t] - v;   // exclusive
}

// per-chunk block scan -> rowptr + cursor; dinv fused here (reads deg anyway)
__global__ void k_scan3(int n, int e) {
    int b = blockIdx.x, t = threadIdx.x;
    int i = b * CH + t;
    int d = (i < n) ? g_deg[i] : 0;
    __shared__ int sh[CH];
    sh[t] = d;
    __syncthreads();
    for (int off = 1; off < CH; off <<= 1) {
        int add = (t >= off) ? sh[t - off] : 0;
        __syncthreads();
        sh[t] += add;
        __syncthreads();
    }
    if (i < n) {
        int run = g_csums[b] + sh[t] - d;   // exclusive
        g_rowptr[i] = run;
        g_cursor[i] = run;
        g_dinv[i] = rsqrtf((float)(d + 1));  // +1 self-loop
    }
    if (b == 0 && t == 0) g_rowptr[n] = e;
}

__global__ void k_scatter(const int* __restrict__ src,
                          const int* __restrict__ dst, int e, int n) {
    int i = blockIdx.x * blockDim.x + threadIdx.x;
    if (i >= e) return;
    int d = dst[i];
    int s = src[i];
    if ((unsigned)d >= (unsigned)n || (unsigned)s >= (unsigned)n) return;
    int pos = atomicAdd(&g_cursor[d], 1);
    if ((unsigned)pos < (unsigned)NE) g_csr[pos] = s;
}

// -------- GEMM: g_hn[row] = fp16((x[row] @ W) * dinv[row]) ----------------
// One thread per row; packed fma.rn.f32x2 (FFMA2, 2x fp32 FMA throughput).
// W staged in shared as float2 column-pairs -> LDS.64 feeds f32x2 directly.
__global__ void __launch_bounds__(128) k_gemm(
    const float* __restrict__ emb, const float* __restrict__ W,
    int layer, int n) {
    __shared__ unsigned long long Ws[64 * 32];   // float2 pairs (cols 2j,2j+1)
    const unsigned long long* Wp = reinterpret_cast<const unsigned long long*>(W);
    for (int t = threadIdx.x; t < 2048; t += blockDim.x) Ws[t] = Wp[t];
    __syncthreads();
    int row = blockIdx.x * blockDim.x + threadIdx.x;
    if (row >= n) return;
    const float* x = (layer == 0) ? emb : g_h1;
    const float* xr = x + (size_t)row * DD;

    unsigned long long acc[32];
#pragma unroll
    for (int j = 0; j < 32; j++) acc[j] = 0ULL;    // (0.f,0.f)

#pragma unroll 4
    for (int k = 0; k < 64; k++) {
        float xv = xr[k];
        unsigned long long x2;
        asm("mov.b64 %0, {%1, %1};" : "=l"(x2) : "f"(xv));
#pragma unroll
        for (int j = 0; j < 32; j++) {
            asm("fma.rn.f32x2 %0, %1, %2, %0;" : "+l"(acc[j]) : "l"(Ws[k * 32 + j]), "l"(x2));
        }
    }
    float di = g_dinv[row];
    unsigned long long di2;
    asm("mov.b64 %0, {%1, %1};" : "=l"(di2) : "f"(di));

    uint4* op = reinterpret_cast<uint4*>(g_hn + (size_t)row * 32);
#pragma unroll
    for (int j4 = 0; j4 < 8; j4++) {
        uint4 pk;
        unsigned r[4];
#pragma unroll
        for (int q = 0; q < 4; q++) {
            unsigned long long a = acc[j4 * 4 + q];
            asm("mul.rn.f32x2 %0, %0, %1;" : "+l"(a) : "l"(di2));
            float lo, hi;
            asm("mov.b64 {%0, %1}, %2;" : "=f"(lo), "=f"(hi) : "l"(a));
            __half2 hv = __floats2half2_rn(lo, hi);
            r[q] = *reinterpret_cast<unsigned*>(&hv);
        }
        pk.x = r[0]; pk.y = r[1]; pk.z = r[2]; pk.w = r[3];
        op[j4] = pk;
    }
}

// ---- aggregation: out = relu(dinv[i]*(hn[i] + sum_nbr hn[s]) + b) ----
// 32 threads per node, each owns a half2 column pair; fp32 accumulation.
// layer==0 writes g_h1 (fp32); layer==1 writes d_out.
__global__ void __launch_bounds__(256) k_agg(
    const float* __restrict__ b, float* __restrict__ dout,
    int layer, int n) {
    int tid = blockIdx.x * blockDim.x + threadIdx.x;
    int node = tid >> 5;
    int lane = tid & 31;
    if (node >= n) return;
    float* out = (layer == 0) ? g_h1 : dout;
    const __half2* hn = g_hn;
    int p = g_rowptr[node];
    int end = g_rowptr[node + 1];

    float2 s0 = __half22float2(hn[(size_t)node * 32 + lane]);  // self-loop
    float ax0 = s0.x, ay0 = s0.y, ax1 = 0.f, ay1 = 0.f;
    for (; p + 2 <= end; p += 2) {
        int n0 = g_csr[p];
        int n1 = g_csr[p + 1];
        float2 f0 = __half22float2(hn[(size_t)n0 * 32 + lane]);
        float2 f1 = __half22float2(hn[(size_t)n1 * 32 + lane]);
        ax0 += f0.x; ay0 += f0.y;
        ax1 += f1.x; ay1 += f1.y;
    }
    if (p < end) {
        int n0 = g_csr[p];
        float2 f0 = __half22float2(hn[(size_t)n0 * 32 + lane]);
        ax0 += f0.x; ay0 += f0.y;
    }
    float di = g_dinv[node];
    float vx = (ax0 + ax1) * di + b[lane * 2];
    float vy = (ay0 + ay1) * di + b[lane * 2 + 1];
    float2* op = reinterpret_cast<float2*>(out + (size_t)node * DD);
    op[lane] = make_float2(fmaxf(vx, 0.f), fmaxf(vy, 0.f));
}

// ---------------- launch (ONLY kernel launches — nothing else) ----------------
extern "C" void kernel_launch(void* const* d_in, const int* in_sizes, int n_in,
                              void* d_out, int out_size) {
    const float* emb = (const float*)d_in[0];
    const int*   ei  = (const int*)d_in[1];     // int32 (JAX x64 disabled)
    const float* W1  = (const float*)d_in[2];
    const float* b1  = (const float*)d_in[3];
    const float* W2  = (const float*)d_in[4];
    const float* b2  = (const float*)d_in[5];
    float*       out = (float*)d_out;

    int N = in_sizes[0] / DD;
    int E = in_sizes[1] / 2;
    const int* srcp = ei;       // edge_index[0]
    const int* dstp = ei + E;   // edge_index[1]
    int nch = (N + CH - 1) / CH;

    // graph preprocessing
    k_init<<<(N + 255) / 256, 256>>>(N);
    k_hist<<<(E + 255) / 256, 256>>>(dstp, E, N);
    k_scan1<<<nch, CH>>>(N);
    k_scan2<<<1, 1024>>>(nch);
    k_scan3<<<nch, CH>>>(N, E);
    k_scatter<<<(E + 255) / 256, 256>>>(srcp, dstp, E, N);

    // layer 1: g_hn = fp16((emb @ W1)*dinv) ; g_h1 = relu(dinv*sum + b1)
    k_gemm<<<(N + 127) / 128, 128>>>(emb, W1, 0, N);
    k_agg<<<(N * 32 + 255) / 256, 256>>>(b1, out, 0, N);
    // layer 2: g_hn = fp16((g_h1 @ W2)*dinv) ; out = relu(dinv*sum + b2)
    k_gemm<<<(N + 127) / 128, 128>>>(emb, W2, 1, N);
    k_agg<<<(N * 32 + 255) / 256, 256>>>(b2, out, 1, N);
}

// round 6
// speedup vs baseline: 1.7577x; 1.2918x over previous
#include <cuda_runtime.h>
#include <cuda_fp16.h>
#include <cstdint>

// Problem constants (fixed by the dataset)
#define NN 100000
#define NE 1600000
#define DD 64
#define CH 128                        // scan chunk size

// ---------------- device scratch (no allocations allowed) ----------------
// Referenced ONLY inside device code; kernel_launch passes only harness
// pointers + scalars (device-symbol host args fault with 717).
// g_deg relies on BSS zero-init; k_finalize re-zeroes it every replay.
__device__ __align__(256) int     g_deg[NN];
__device__ __align__(256) float   g_dinv[NN];
__device__ __align__(256) int     g_rowptr[NN + 1];
__device__ __align__(256) int     g_cursor[NN];
__device__ __align__(256) int     g_csums[1024];
__device__ __align__(256) int     g_csr[NE];
__device__ __align__(256) __half2 g_hn[(size_t)NN * 32];  // (x@W)*dinv, fp16
__device__ __align__(256) float   g_h1[(size_t)NN * DD];  // layer-1 output

// ---------------- graph preprocessing (edge_index is int32) ----------------

__global__ void k_hist(const int* __restrict__ dst, int e, int n) {
    int i = blockIdx.x * blockDim.x + threadIdx.x;
    if (i >= e) return;
    int d = dst[i];
    if ((unsigned)d < (unsigned)n) atomicAdd(&g_deg[d], 1);
}

// per-chunk degree sums (one block per chunk, shuffle reduce)
__global__ void k_chunksum(int n) {
    int b = blockIdx.x, t = threadIdx.x;
    int i = b * CH + t;
    int v = (i < n) ? g_deg[i] : 0;
#pragma unroll
    for (int o = 16; o; o >>= 1) v += __shfl_down_sync(0xFFFFFFFFu, v, o);
    __shared__ int ws[4];
    if ((t & 31) == 0) ws[t >> 5] = v;
    __syncthreads();
    if (t == 0) g_csums[b] = ws[0] + ws[1] + ws[2] + ws[3];
}

// per-chunk: redundant prefix over csums + chunk-internal scan.
// Writes rowptr/cursor/dinv and re-zeroes g_deg (replay invariant).
__global__ void k_finalize(int n, int nch, int e) {
    int b = blockIdx.x, t = threadIdx.x;
    // prefix = sum of csums[0..b)
    int s = 0;
    for (int j = t; j < b; j += CH) s += g_csums[j];
#pragma unroll
    for (int o = 16; o; o >>= 1) s += __shfl_down_sync(0xFFFFFFFFu, s, o);
    __shared__ int ws[4];
    __shared__ int pre;
    if ((t & 31) == 0) ws[t >> 5] = s;
    __syncthreads();
    if (t == 0) pre = ws[0] + ws[1] + ws[2] + ws[3];
    __syncthreads();
    // chunk-internal inclusive scan
    int i = b * CH + t;
    int d = (i < n) ? g_deg[i] : 0;
    __shared__ int sh[CH];
    sh[t] = d;
    __syncthreads();
    for (int off = 1; off < CH; off <<= 1) {
        int add = (t >= off) ? sh[t - off] : 0;
        __syncthreads();
        sh[t] += add;
        __syncthreads();
    }
    if (i < n) {
        int run = pre + sh[t] - d;   // exclusive
        g_rowptr[i] = run;
        g_cursor[i] = run;
        g_dinv[i] = rsqrtf((float)(d + 1));  // +1 self-loop
        g_deg[i] = 0;                        // clean for next replay
    }
    if (b == 0 && t == 0) g_rowptr[n] = e;
}

__global__ void k_scatter(const int* __restrict__ src,
                          const int* __restrict__ dst, int e, int n) {
    int i = blockIdx.x * blockDim.x + threadIdx.x;
    if (i >= e) return;
    int d = dst[i];
    int s = src[i];
    if ((unsigned)d >= (unsigned)n || (unsigned)s >= (unsigned)n) return;
    int pos = atomicAdd(&g_cursor[d], 1);
    if ((unsigned)pos < (unsigned)NE) g_csr[pos] = s;
}

// -------- GEMM: g_hn[row] = fp16((x[row] @ W) * dinv[row]) ----------------
// One thread per row; fma.rn.f32x2 (FFMA2). x read as float4 (LDG.128:
// 512 L1 wavefronts/warp instead of 2048 with scalar loads).
__global__ void __launch_bounds__(128) k_gemm(
    const float* __restrict__ emb, const float* __restrict__ W,
    int layer, int n) {
    __shared__ unsigned long long Ws[64 * 32];   // float2 col pairs
    const unsigned long long* Wp = reinterpret_cast<const unsigned long long*>(W);
    for (int t = threadIdx.x; t < 2048; t += blockDim.x) Ws[t] = Wp[t];
    __syncthreads();
    int row = blockIdx.x * blockDim.x + threadIdx.x;
    if (row >= n) return;
    const float* x = (layer == 0) ? emb : g_h1;
    const float4* x4 = reinterpret_cast<const float4*>(x + (size_t)row * DD);

    unsigned long long acc[32];
#pragma unroll
    for (int j = 0; j < 32; j++) acc[j] = 0ULL;

#pragma unroll 4
    for (int kk = 0; kk < 16; kk++) {
        float4 xq = x4[kk];
        float xs[4] = {xq.x, xq.y, xq.z, xq.w};
#pragma unroll
        for (int q = 0; q < 4; q++) {
            unsigned long long x2;
            asm("mov.b64 %0, {%1, %1};" : "=l"(x2) : "f"(xs[q]));
            int k = kk * 4 + q;
#pragma unroll
            for (int j = 0; j < 32; j++) {
                asm("fma.rn.f32x2 %0, %1, %2, %0;"
                    : "+l"(acc[j]) : "l"(Ws[k * 32 + j]), "l"(x2));
            }
        }
    }
    float di = g_dinv[row];
    unsigned long long di2;
    asm("mov.b64 %0, {%1, %1};" : "=l"(di2) : "f"(di));

    uint4* op = reinterpret_cast<uint4*>(g_hn + (size_t)row * 32);
#pragma unroll
    for (int j4 = 0; j4 < 8; j4++) {
        unsigned r[4];
#pragma unroll
        for (int q = 0; q < 4; q++) {
            unsigned long long a = acc[j4 * 4 + q];
            asm("mul.rn.f32x2 %0, %0, %1;" : "+l"(a) : "l"(di2));
            float lo, hi;
            asm("mov.b64 {%0, %1}, %2;" : "=f"(lo), "=f"(hi) : "l"(a));
            __half2 hv = __floats2half2_rn(lo, hi);
            r[q] = *reinterpret_cast<unsigned*>(&hv);
        }
        uint4 pk; pk.x = r[0]; pk.y = r[1]; pk.z = r[2]; pk.w = r[3];
        op[j4] = pk;
    }
}

// ---- aggregation: out = relu(dinv[i]*(hn[i] + sum_nbr hn[s]) + b) ----
// 8 lanes per node (4 nodes/warp), uint4 row gathers (128B per node/iter),
// 4-deep unroll -> up to 16 outstanding gathers per warp. fp32 accumulate.
__global__ void __launch_bounds__(256) k_agg(
    const float* __restrict__ b, float* __restrict__ dout,
    int layer, int n) {
    int tid = blockIdx.x * blockDim.x + threadIdx.x;
    int node = tid >> 3;
    int sub = tid & 7;                 // owns half2[4*sub .. 4*sub+3]
    if (node >= n) return;
    float* out = (layer == 0) ? g_h1 : dout;
    const uint4* hn4 = reinterpret_cast<const uint4*>(g_hn);

    int p = g_rowptr[node];
    int end = g_rowptr[node + 1];

    uint4 uself = hn4[(size_t)node * 8 + sub];
    float2 a0 = __half22float2(*reinterpret_cast<__half2*>(&uself.x));
    float2 a1 = __half22float2(*reinterpret_cast<__half2*>(&uself.y));
    float2 a2 = __half22float2(*reinterpret_cast<__half2*>(&uself.z));
    float2 a3 = __half22float2(*reinterpret_cast<__half2*>(&uself.w));
    float2 c0 = {0.f, 0.f}, c1 = {0.f, 0.f}, c2 = {0.f, 0.f}, c3 = {0.f, 0.f};

#define ACC_U4(U, X0, X1, X2, X3)                                         \
    {                                                                     \
        float2 f0 = __half22float2(*reinterpret_cast<__half2*>(&(U).x));  \
        float2 f1 = __half22float2(*reinterpret_cast<__half2*>(&(U).y));  \
        float2 f2 = __half22float2(*reinterpret_cast<__half2*>(&(U).z));  \
        float2 f3 = __half22float2(*reinterpret_cast<__half2*>(&(U).w));  \
        X0.x += f0.x; X0.y += f0.y; X1.x += f1.x; X1.y += f1.y;           \
        X2.x += f2.x; X2.y += f2.y; X3.x += f3.x; X3.y += f3.y;           \
    }

    for (; p + 4 <= end; p += 4) {
        int n0 = g_csr[p], n1 = g_csr[p + 1], n2 = g_csr[p + 2], n3 = g_csr[p + 3];
        uint4 u0 = hn4[(size_t)n0 * 8 + sub];
        uint4 u1 = hn4[(size_t)n1 * 8 + sub];
        uint4 u2 = hn4[(size_t)n2 * 8 + sub];
        uint4 u3 = hn4[(size_t)n3 * 8 + sub];
        ACC_U4(u0, a0, a1, a2, a3)
        ACC_U4(u1, c0, c1, c2, c3)
        ACC_U4(u2, a0, a1, a2, a3)
        ACC_U4(u3, c0, c1, c2, c3)
    }
    for (; p < end; p++) {
        int n0 = g_csr[p];
        uint4 u0 = hn4[(size_t)n0 * 8 + sub];
        ACC_U4(u0, a0, a1, a2, a3)
    }
#undef ACC_U4

    float di = g_dinv[node];
    const float4* b4 = reinterpret_cast<const float4*>(b);
    float4 bA = b4[sub * 2], bB = b4[sub * 2 + 1];
    float4 oA, oB;
    oA.x = fmaxf((a0.x + c0.x) * di + bA.x, 0.f);
    oA.y = fmaxf((a0.y + c0.y) * di + bA.y, 0.f);
    oA.z = fmaxf((a1.x + c1.x) * di + bA.z, 0.f);
    oA.w = fmaxf((a1.y + c1.y) * di + bA.w, 0.f);
    oB.x = fmaxf((a2.x + c2.x) * di + bB.x, 0.f);
    oB.y = fmaxf((a2.y + c2.y) * di + bB.y, 0.f);
    oB.z = fmaxf((a3.x + c3.x) * di + bB.z, 0.f);
    oB.w = fmaxf((a3.y + c3.y) * di + bB.w, 0.f);
    float4* op = reinterpret_cast<float4*>(out + (size_t)node * DD + sub * 8);
    op[0] = oA;
    op[1] = oB;
}

// ---------------- launch (ONLY kernel launches — nothing else) ----------------
extern "C" void kernel_launch(void* const* d_in, const int* in_sizes, int n_in,
                              void* d_out, int out_size) {
    const float* emb = (const float*)d_in[0];
    const int*   ei  = (const int*)d_in[1];     // int32 (JAX x64 disabled)
    const float* W1  = (const float*)d_in[2];
    const float* b1  = (const float*)d_in[3];
    const float* W2  = (const float*)d_in[4];
    const float* b2  = (const float*)d_in[5];
    float*       out = (float*)d_out;

    int N = in_sizes[0] / DD;
    int E = in_sizes[1] / 2;
    const int* srcp = ei;       // edge_index[0]
    const int* dstp = ei + E;   // edge_index[1]
    int nch = (N + CH - 1) / CH;

    // preprocessing: 4 launches (g_deg starts zero; k_finalize re-zeroes it)
    k_hist<<<(E + 255) / 256, 256>>>(dstp, E, N);
    k_chunksum<<<nch, CH>>>(N);
    k_finalize<<<nch, CH>>>(N, nch, E);
    k_scatter<<<(E + 255) / 256, 256>>>(srcp, dstp, E, N);   // launch #4 -> profiled

    // layer 1
    k_gemm<<<(N + 127) / 128, 128>>>(emb, W1, 0, N);
    k_agg<<<(N * 8 + 255) / 256, 256>>>(b1, out, 0, N);
    // layer 2
    k_gemm<<<(N + 127) / 128, 128>>>(emb, W2, 1, N);
    k_agg<<<(N * 8 + 255) / 256, 256>>>(b2, out, 1, N);
}

// round 7
// speedup vs baseline: 1.8445x; 1.0494x over previous
#include <cuda_runtime.h>
#include <cuda_fp16.h>
#include <cstdint>

// Problem constants (fixed by the dataset)
#define NN 100000
#define NE 1600000
#define DD 64
#define CAP 64          // bucket capacity per node (Poisson(16): P(deg>64)~2e-22)

// ---------------- device scratch (no allocations allowed) ----------------
// Referenced ONLY inside device code. g_cnt relies on BSS zero-init; AGG
// layer-2 re-zeroes it after its final read (replay invariant).
__device__ __align__(256) int     g_cnt[NN];
__device__ __align__(256) int     g_bkt[(size_t)NN * CAP];   // bucket CSR
__device__ __align__(256) __half2 g_hn[(size_t)NN * 32];     // (x@W)*dinv, fp16
__device__ __align__(256) float   g_h1[(size_t)NN * DD];     // layer-1 output

// ------------- single-pass bucket scatter (edge_index is int32) -------------
// 2 edges per thread via int2 loads; slot from atomicAdd on per-dst counter.
__global__ void k_scatter(const int* __restrict__ src,
                          const int* __restrict__ dst, int e2, int n) {
    int i = blockIdx.x * blockDim.x + threadIdx.x;
    if (i >= e2) return;
    int2 s2 = reinterpret_cast<const int2*>(src)[i];
    int2 d2 = reinterpret_cast<const int2*>(dst)[i];
#pragma unroll
    for (int q = 0; q < 2; q++) {
        int d = q ? d2.y : d2.x;
        int s = q ? s2.y : s2.x;
        if ((unsigned)d >= (unsigned)n || (unsigned)s >= (unsigned)n) continue;
        int slot = atomicAdd(&g_cnt[d], 1);
        if (slot < CAP) g_bkt[(size_t)d * CAP + slot] = s;
    }
}

// -------- GEMM: g_hn[row] = fp16((x[row] @ W) * rsqrt(deg[row]+1)) ---------
// One thread per row; fma.rn.f32x2 (FFMA2); x read as float4 (LDG.128).
__global__ void __launch_bounds__(128) k_gemm(
    const float* __restrict__ emb, const float* __restrict__ W,
    int layer, int n) {
    __shared__ unsigned long long Ws[64 * 32];   // float2 col pairs
    const unsigned long long* Wp = reinterpret_cast<const unsigned long long*>(W);
    for (int t = threadIdx.x; t < 2048; t += blockDim.x) Ws[t] = Wp[t];
    __syncthreads();
    int row = blockIdx.x * blockDim.x + threadIdx.x;
    if (row >= n) return;
    const float* x = (layer == 0) ? emb : g_h1;
    const float4* x4 = reinterpret_cast<const float4*>(x + (size_t)row * DD);

    unsigned long long acc[32];
#pragma unroll
    for (int j = 0; j < 32; j++) acc[j] = 0ULL;

#pragma unroll 4
    for (int kk = 0; kk < 16; kk++) {
        float4 xq = x4[kk];
        float xs[4] = {xq.x, xq.y, xq.z, xq.w};
#pragma unroll
        for (int q = 0; q < 4; q++) {
            unsigned long long x2;
            asm("mov.b64 %0, {%1, %1};" : "=l"(x2) : "f"(xs[q]));
            int k = kk * 4 + q;
#pragma unroll
            for (int j = 0; j < 32; j++) {
                asm("fma.rn.f32x2 %0, %1, %2, %0;"
                    : "+l"(acc[j]) : "l"(Ws[k * 32 + j]), "l"(x2));
            }
        }
    }
    float di = rsqrtf((float)(g_cnt[row] + 1));   // dinv from degree count
    unsigned long long di2;
    asm("mov.b64 %0, {%1, %1};" : "=l"(di2) : "f"(di));

    uint4* op = reinterpret_cast<uint4*>(g_hn + (size_t)row * 32);
#pragma unroll
    for (int j4 = 0; j4 < 8; j4++) {
        unsigned r[4];
#pragma unroll
        for (int q = 0; q < 4; q++) {
            unsigned long long a = acc[j4 * 4 + q];
            asm("mul.rn.f32x2 %0, %0, %1;" : "+l"(a) : "l"(di2));
            float lo, hi;
            asm("mov.b64 {%0, %1}, %2;" : "=f"(lo), "=f"(hi) : "l"(a));
            __half2 hv = __floats2half2_rn(lo, hi);
            r[q] = *reinterpret_cast<unsigned*>(&hv);
        }
        uint4 pk; pk.x = r[0]; pk.y = r[1]; pk.z = r[2]; pk.w = r[3];
        op[j4] = pk;
    }
}

// ---- aggregation: out = relu(dinv[i]*(hn[i] + sum_nbr hn[s]) + b) ----
// 8 lanes per node (4 nodes/warp), uint4 row gathers, contiguous bucket
// indices read as broadcast int4 (1 index load per 4 edges). fp32 accumulate.
// layer==1 additionally zeroes g_cnt[node] (replay invariant) + writes d_out.
__global__ void __launch_bounds__(256) k_agg(
    const float* __restrict__ b, float* __restrict__ dout,
    int layer, int n) {
    int tid = blockIdx.x * blockDim.x + threadIdx.x;
    int node = tid >> 3;
    int sub = tid & 7;                 // owns half2[4*sub .. 4*sub+3]
    if (node >= n) return;
    float* out = (layer == 0) ? g_h1 : dout;
    const uint4* hn4 = reinterpret_cast<const uint4*>(g_hn);

    int cnt = g_cnt[node];
    float di = rsqrtf((float)(cnt + 1));
    int len = min(cnt, CAP);
    const int4* bp = reinterpret_cast<const int4*>(g_bkt + (size_t)node * CAP);

    uint4 uself = hn4[(size_t)node * 8 + sub];
    float2 a0 = __half22float2(*reinterpret_cast<__half2*>(&uself.x));
    float2 a1 = __half22float2(*reinterpret_cast<__half2*>(&uself.y));
    float2 a2 = __half22float2(*reinterpret_cast<__half2*>(&uself.z));
    float2 a3 = __half22float2(*reinterpret_cast<__half2*>(&uself.w));
    float2 c0 = {0.f, 0.f}, c1 = {0.f, 0.f}, c2 = {0.f, 0.f}, c3 = {0.f, 0.f};

#define ACC_U4(U, X0, X1, X2, X3)                                         \
    {                                                                     \
        float2 f0 = __half22float2(*reinterpret_cast<__half2*>(&(U).x));  \
        float2 f1 = __half22float2(*reinterpret_cast<__half2*>(&(U).y));  \
        float2 f2 = __half22float2(*reinterpret_cast<__half2*>(&(U).z));  \
        float2 f3 = __half22float2(*reinterpret_cast<__half2*>(&(U).w));  \
        X0.x += f0.x; X0.y += f0.y; X1.x += f1.x; X1.y += f1.y;           \
        X2.x += f2.x; X2.y += f2.y; X3.x += f3.x; X3.y += f3.y;           \
    }

    int p = 0;
    for (; p + 4 <= len; p += 4) {
        int4 e = bp[p >> 2];                      // broadcast across 8 lanes
        uint4 u0 = hn4[(size_t)e.x * 8 + sub];
        uint4 u1 = hn4[(size_t)e.y * 8 + sub];
        uint4 u2 = hn4[(size_t)e.z * 8 + sub];
        uint4 u3 = hn4[(size_t)e.w * 8 + sub];
        ACC_U4(u0, a0, a1, a2, a3)
        ACC_U4(u1, c0, c1, c2, c3)
        ACC_U4(u2, a0, a1, a2, a3)
        ACC_U4(u3, c0, c1, c2, c3)
    }
    for (; p < len; p++) {
        int s = g_bkt[(size_t)node * CAP + p];
        uint4 u0 = hn4[(size_t)s * 8 + sub];
        ACC_U4(u0, a0, a1, a2, a3)
    }
#undef ACC_U4

    if (layer == 1 && sub == 0) g_cnt[node] = 0;   // clean for next replay

    const float4* b4 = reinterpret_cast<const float4*>(b);
    float4 bA = b4[sub * 2], bB = b4[sub * 2 + 1];
    float4 oA, oB;
    oA.x = fmaxf((a0.x + c0.x) * di + bA.x, 0.f);
    oA.y = fmaxf((a0.y + c0.y) * di + bA.y, 0.f);
    oA.z = fmaxf((a1.x + c1.x) * di + bA.z, 0.f);
    oA.w = fmaxf((a1.y + c1.y) * di + bA.w, 0.f);
    oB.x = fmaxf((a2.x + c2.x) * di + bB.x, 0.f);
    oB.y = fmaxf((a2.y + c2.y) * di + bB.y, 0.f);
    oB.z = fmaxf((a3.x + c3.x) * di + bB.z, 0.f);
    oB.w = fmaxf((a3.y + c3.y) * di + bB.w, 0.f);
    float4* op = reinterpret_cast<float4*>(out + (size_t)node * DD + sub * 8);
    op[0] = oA;
    op[1] = oB;
}

// ---------------- launch (ONLY kernel launches — nothing else) ----------------
extern "C" void kernel_launch(void* const* d_in, const int* in_sizes, int n_in,
                              void* d_out, int out_size) {
    const float* emb = (const float*)d_in[0];
    const int*   ei  = (const int*)d_in[1];     // int32 (JAX x64 disabled)
    const float* W1  = (const float*)d_in[2];
    const float* b1  = (const float*)d_in[3];
    const float* W2  = (const float*)d_in[4];
    const float* b2  = (const float*)d_in[5];
    float*       out = (float*)d_out;

    int N = in_sizes[0] / DD;
    int E = in_sizes[1] / 2;
    const int* srcp = ei;       // edge_index[0]
    const int* dstp = ei + E;   // edge_index[1]
    int e2 = E / 2;             // 2 edges per thread

    // single-pass preprocessing: bucket CSR + degree counts (1 launch)
    k_scatter<<<(e2 + 255) / 256, 256>>>(srcp, dstp, e2, N);

    // layer 1
    k_gemm<<<(N + 127) / 128, 128>>>(emb, W1, 0, N);
    k_agg<<<(N * 8 + 255) / 256, 256>>>(b1, out, 0, N);
    // layer 2  (launch #4 -> profiled next round)
    k_gemm<<<(N + 127) / 128, 128>>>(emb, W2, 1, N);
    k_agg<<<(N * 8 + 255) / 256, 256>>>(b2, out, 1, N);
}

// round 8
// speedup vs baseline: 2.0867x; 1.1313x over previous
#include <cuda_runtime.h>
#include <cuda_fp16.h>
#include <cstdint>

// Problem constants (fixed by the dataset)
#define NN 100000
#define NE 1600000
#define DD 64
#define CAP 64          // bucket capacity per node (Poisson(16): P(deg>64)~2e-22)

// ---------------- device scratch (no allocations allowed) ----------------
// g_cnt relies on BSS zero-init; AGG layer-2 re-zeroes it (replay invariant).
__device__ __align__(256) int     g_cnt[NN];
__device__ __align__(256) int     g_bkt[(size_t)NN * CAP];   // bucket CSR
__device__ __align__(256) __half2 g_hn[(size_t)NN * 32];     // (x@W)*dinv, fp16
__device__ __align__(256) float   g_h1[(size_t)NN * DD];     // layer-1 output

// ------------- single-pass bucket scatter (edge_index is int32) -------------
__global__ void k_scatter(const int* __restrict__ src,
                          const int* __restrict__ dst, int e2, int n) {
    int i = blockIdx.x * blockDim.x + threadIdx.x;
    if (i >= e2) return;
    int2 s2 = reinterpret_cast<const int2*>(src)[i];
    int2 d2 = reinterpret_cast<const int2*>(dst)[i];
#pragma unroll
    for (int q = 0; q < 2; q++) {
        int d = q ? d2.y : d2.x;
        int s = q ? s2.y : s2.x;
        if ((unsigned)d >= (unsigned)n || (unsigned)s >= (unsigned)n) continue;
        int slot = atomicAdd(&g_cnt[d], 1);
        if (slot < CAP) g_bkt[(size_t)d * CAP + slot] = s;
    }
}

// -------- GEMM: g_hn[row] = fp16((x[row] @ W) * rsqrt(deg[row]+1)) ---------
// 2 rows per thread (r, r+128); W in shared as ulonglong2 (LDS.128 = 4 cols);
// one W load feeds 4 FFMA2 -> shared wavefronts/row cut 4x vs R7 (was the
// 60% L1 bottleneck). fma.rn.f32x2 packed math throughout.
__global__ void __launch_bounds__(128) k_gemm(
    const float* __restrict__ emb, const float* __restrict__ W,
    int layer, int n) {
    __shared__ ulonglong2 Ws[64 * 16];   // [k][jj]: cols 4jj..4jj+3
    const ulonglong2* Wp = reinterpret_cast<const ulonglong2*>(W);
    for (int t = threadIdx.x; t < 1024; t += blockDim.x) Ws[t] = Wp[t];
    __syncthreads();

    const float* x = (layer == 0) ? emb : g_h1;
    int r0 = blockIdx.x * 256 + threadIdx.x;
    int r1 = r0 + 128;
    bool v0 = r0 < n, v1 = r1 < n;
    const float4* x40 = reinterpret_cast<const float4*>(x + (size_t)r0 * DD);
    const float4* x41 = reinterpret_cast<const float4*>(x + (size_t)r1 * DD);

    unsigned long long a0[32], a1[32];
#pragma unroll
    for (int j = 0; j < 32; j++) { a0[j] = 0ULL; a1[j] = 0ULL; }

#pragma unroll 2
    for (int kk = 0; kk < 16; kk++) {
        float4 xqa = v0 ? x40[kk] : make_float4(0.f, 0.f, 0.f, 0.f);
        float4 xqb = v1 ? x41[kk] : make_float4(0.f, 0.f, 0.f, 0.f);
        float xsa[4] = {xqa.x, xqa.y, xqa.z, xqa.w};
        float xsb[4] = {xqb.x, xqb.y, xqb.z, xqb.w};
#pragma unroll
        for (int q = 0; q < 4; q++) {
            unsigned long long xa2, xb2;
            asm("mov.b64 %0, {%1, %1};" : "=l"(xa2) : "f"(xsa[q]));
            asm("mov.b64 %0, {%1, %1};" : "=l"(xb2) : "f"(xsb[q]));
            int k = kk * 4 + q;
#pragma unroll
            for (int jj = 0; jj < 16; jj++) {
                ulonglong2 w = Ws[k * 16 + jj];   // 1 LDS.128 -> 4 FFMA2
                asm("fma.rn.f32x2 %0, %1, %2, %0;" : "+l"(a0[jj * 2])     : "l"(w.x), "l"(xa2));
                asm("fma.rn.f32x2 %0, %1, %2, %0;" : "+l"(a0[jj * 2 + 1]) : "l"(w.y), "l"(xa2));
                asm("fma.rn.f32x2 %0, %1, %2, %0;" : "+l"(a1[jj * 2])     : "l"(w.x), "l"(xb2));
                asm("fma.rn.f32x2 %0, %1, %2, %0;" : "+l"(a1[jj * 2 + 1]) : "l"(w.y), "l"(xb2));
            }
        }
    }

#pragma unroll
    for (int rsel = 0; rsel < 2; rsel++) {
        int row = rsel ? r1 : r0;
        if (row >= n) continue;
        unsigned long long* acc = rsel ? a1 : a0;
        float di = rsqrtf((float)(g_cnt[row] + 1));
        unsigned long long di2;
        asm("mov.b64 %0, {%1, %1};" : "=l"(di2) : "f"(di));
        uint4* op = reinterpret_cast<uint4*>(g_hn + (size_t)row * 32);
#pragma unroll
        for (int j4 = 0; j4 < 8; j4++) {
            unsigned r[4];
#pragma unroll
            for (int q = 0; q < 4; q++) {
                unsigned long long a = acc[j4 * 4 + q];
                asm("mul.rn.f32x2 %0, %0, %1;" : "+l"(a) : "l"(di2));
                float lo, hi;
                asm("mov.b64 {%0, %1}, %2;" : "=f"(lo), "=f"(hi) : "l"(a));
                __half2 hv = __floats2half2_rn(lo, hi);
                r[q] = *reinterpret_cast<unsigned*>(&hv);
            }
            uint4 pk; pk.x = r[0]; pk.y = r[1]; pk.z = r[2]; pk.w = r[3];
            op[j4] = pk;
        }
    }
}

// ---- aggregation: out = relu(dinv[i]*(hn[i] + sum_nbr hn[s]) + b) ----
// 8 lanes/node (4 nodes/warp), uint4 row gathers, bucket indices as int4.
// layer==1 zeroes g_cnt[node] after last read (replay invariant).
__global__ void __launch_bounds__(256) k_agg(
    const float* __restrict__ b, float* __restrict__ dout,
    int layer, int n) {
    int tid = blockIdx.x * blockDim.x + threadIdx.x;
    int node = tid >> 3;
    int sub = tid & 7;                 // owns half2[4*sub .. 4*sub+3]
    if (node >= n) return;
    float* out = (layer == 0) ? g_h1 : dout;
    const uint4* hn4 = reinterpret_cast<const uint4*>(g_hn);

    int cnt = g_cnt[node];
    float di = rsqrtf((float)(cnt + 1));
    int len = min(cnt, CAP);
    const int4* bp = reinterpret_cast<const int4*>(g_bkt + (size_t)node * CAP);

    uint4 uself = hn4[(size_t)node * 8 + sub];
    float2 a0 = __half22float2(*reinterpret_cast<__half2*>(&uself.x));
    float2 a1 = __half22float2(*reinterpret_cast<__half2*>(&uself.y));
    float2 a2 = __half22float2(*reinterpret_cast<__half2*>(&uself.z));
    float2 a3 = __half22float2(*reinterpret_cast<__half2*>(&uself.w));
    float2 c0 = {0.f, 0.f}, c1 = {0.f, 0.f}, c2 = {0.f, 0.f}, c3 = {0.f, 0.f};

#define ACC_U4(U, X0, X1, X2, X3)                                         \
    {                                                                     \
        float2 f0 = __half22float2(*reinterpret_cast<__half2*>(&(U).x));  \
        float2 f1 = __half22float2(*reinterpret_cast<__half2*>(&(U).y));  \
        float2 f2 = __half22float2(*reinterpret_cast<__half2*>(&(U).z));  \
        float2 f3 = __half22float2(*reinterpret_cast<__half2*>(&(U).w));  \
        X0.x += f0.x; X0.y += f0.y; X1.x += f1.x; X1.y += f1.y;           \
        X2.x += f2.x; X2.y += f2.y; X3.x += f3.x; X3.y += f3.y;           \
    }

    int p = 0;
    for (; p + 4 <= len; p += 4) {
        int4 e = bp[p >> 2];                      // broadcast across 8 lanes
        uint4 u0 = hn4[(size_t)e.x * 8 + sub];
        uint4 u1 = hn4[(size_t)e.y * 8 + sub];
        uint4 u2 = hn4[(size_t)e.z * 8 + sub];
        uint4 u3 = hn4[(size_t)e.w * 8 + sub];
        ACC_U4(u0, a0, a1, a2, a3)
        ACC_U4(u1, c0, c1, c2, c3)
        ACC_U4(u2, a0, a1, a2, a3)
        ACC_U4(u3, c0, c1, c2, c3)
    }
    for (; p < len; p++) {
        int s = g_bkt[(size_t)node * CAP + p];
        uint4 u0 = hn4[(size_t)s * 8 + sub];
        ACC_U4(u0, a0, a1, a2, a3)
    }
#undef ACC_U4

    if (layer == 1 && sub == 0) g_cnt[node] = 0;   // clean for next replay

    const float4* b4 = reinterpret_cast<const float4*>(b);
    float4 bA = b4[sub * 2], bB = b4[sub * 2 + 1];
    float4 oA, oB;
    oA.x = fmaxf((a0.x + c0.x) * di + bA.x, 0.f);
    oA.y = fmaxf((a0.y + c0.y) * di + bA.y, 0.f);
    oA.z = fmaxf((a1.x + c1.x) * di + bA.z, 0.f);
    oA.w = fmaxf((a1.y + c1.y) * di + bA.w, 0.f);
    oB.x = fmaxf((a2.x + c2.x) * di + bB.x, 0.f);
    oB.y = fmaxf((a2.y + c2.y) * di + bB.y, 0.f);
    oB.z = fmaxf((a3.x + c3.x) * di + bB.z, 0.f);
    oB.w = fmaxf((a3.y + c3.y) * di + bB.w, 0.f);
    float4* op = reinterpret_cast<float4*>(out + (size_t)node * DD + sub * 8);
    op[0] = oA;
    op[1] = oB;
}

// ---------------- launch (ONLY kernel launches — nothing else) ----------------
extern "C" void kernel_launch(void* const* d_in, const int* in_sizes, int n_in,
                              void* d_out, int out_size) {
    const float* emb = (const float*)d_in[0];
    const int*   ei  = (const int*)d_in[1];     // int32 (JAX x64 disabled)
    const float* W1  = (const float*)d_in[2];
    const float* b1  = (const float*)d_in[3];
    const float* W2  = (const float*)d_in[4];
    const float* b2  = (const float*)d_in[5];
    float*       out = (float*)d_out;

    int N = in_sizes[0] / DD;
    int E = in_sizes[1] / 2;
    const int* srcp = ei;       // edge_index[0]
    const int* dstp = ei + E;   // edge_index[1]
    int e2 = E / 2;             // 2 edges per thread

    // single-pass preprocessing: bucket CSR + degree counts (1 launch)
    k_scatter<<<(e2 + 255) / 256, 256>>>(srcp, dstp, e2, N);

    // layer 1
    k_gemm<<<(N + 255) / 256, 128>>>(emb, W1, 0, N);
    k_agg<<<(N * 8 + 255) / 256, 256>>>(b1, out, 0, N);
    // layer 2  (launch #4 -> profiled next round)
    k_gemm<<<(N + 255) / 256, 128>>>(emb, W2, 1, N);
    k_agg<<<(N * 8 + 255) / 256, 256>>>(b2, out, 1, N);
}

// round 9
// speedup vs baseline: 2.5686x; 1.2309x over previous
#include <cuda_runtime.h>
#include <cuda_fp16.h>
#include <cstdint>

// Problem constants (fixed by the dataset)
#define NN 100000
#define NE 1600000
#define DD 64
#define CAP 64          // bucket capacity per node (Poisson(16): P(deg>64)~2e-22)

#define XS_STRIDE 72    // halves; 144B rows: 16B-aligned + conflict-free ldmatrix

// ---------------- device scratch (no allocations allowed) ----------------
// g_cnt relies on BSS zero-init; AGG layer-2 re-zeroes it (replay invariant).
__device__ __align__(256) int     g_cnt[NN];
__device__ __align__(256) int     g_bkt[(size_t)NN * CAP];   // bucket CSR
__device__ __align__(256) __half2 g_hn[(size_t)NN * 32];     // (x@W)*dinv, fp16
__device__ __align__(256) float   g_h1[(size_t)NN * DD];     // layer-1 output

// ------------- single-pass bucket scatter (edge_index is int32) -------------
__global__ void k_scatter(const int* __restrict__ src,
                          const int* __restrict__ dst, int e2, int n) {
    int i = blockIdx.x * blockDim.x + threadIdx.x;
    if (i >= e2) return;
    int2 s2 = reinterpret_cast<const int2*>(src)[i];
    int2 d2 = reinterpret_cast<const int2*>(dst)[i];
#pragma unroll
    for (int q = 0; q < 2; q++) {
        int d = q ? d2.y : d2.x;
        int s = q ? s2.y : s2.x;
        if ((unsigned)d >= (unsigned)n || (unsigned)s >= (unsigned)n) continue;
        int slot = atomicAdd(&g_cnt[d], 1);
        if (slot < CAP) g_bkt[(size_t)d * CAP + slot] = s;
    }
}

// -------- GEMM via tensor cores: g_hn[row] = fp16((x@W) * rsqrt(deg+1)) -----
// Block = 256 threads = 8 warps, 256 rows (32 rows/warp, two m16 tiles).
// x staged fp16 in shared (stride 72 halves); W staged fp16 TRANSPOSED
// (n-major, stride 72) so each B fragment half2 is one conflict-free LDS.32.
// mma.sync.m16n8k16 row.col f32.f16.f16.f32, fp32 accumulate.
__global__ void __launch_bounds__(256) k_gemm(
    const float* __restrict__ emb, const float* __restrict__ W,
    int layer, int n) {
    __shared__ __half xs[256 * XS_STRIDE];       // 36864 B
    __shared__ __half wt[64 * XS_STRIDE];        //  9216 B  (wt[n][k])
    int tid = threadIdx.x;
    const float* x = (layer == 0) ? emb : g_h1;

    // ---- stage x rows -> fp16 shared ----
    int row = blockIdx.x * 256 + tid;
    {
        const float4* xr = reinterpret_cast<const float4*>(x + (size_t)row * DD);
        bool v = row < n;
        __half2* dstp = reinterpret_cast<__half2*>(&xs[tid * XS_STRIDE]);
#pragma unroll
        for (int kk = 0; kk < 16; kk++) {
            float4 q = v ? xr[kk] : make_float4(0.f, 0.f, 0.f, 0.f);
            dstp[kk * 2]     = __floats2half2_rn(q.x, q.y);
            dstp[kk * 2 + 1] = __floats2half2_rn(q.z, q.w);
        }
    }
    // ---- stage W -> fp16 transposed shared (wt[n][k]) ----
    {
        const float4* Wp4 = reinterpret_cast<const float4*>(W);
#pragma unroll
        for (int ii = 0; ii < 4; ii++) {
            int i4 = tid + 256 * ii;             // 1024 float4 total
            float4 wv = Wp4[i4];
            int flat = i4 * 4;
            int k = flat >> 6;
            int nn = flat & 63;
            wt[(nn)     * XS_STRIDE + k] = __float2half_rn(wv.x);
            wt[(nn + 1) * XS_STRIDE + k] = __float2half_rn(wv.y);
            wt[(nn + 2) * XS_STRIDE + k] = __float2half_rn(wv.z);
            wt[(nn + 3) * XS_STRIDE + k] = __float2half_rn(wv.w);
        }
    }
    __syncthreads();

    int wid = tid >> 5, lane = tid & 31;
    int g = lane >> 2, t = lane & 3;
    uint32_t xs_u32 = (uint32_t)__cvta_generic_to_shared(xs);

    // A fragments: [mtile][kchunk][4 regs] via ldmatrix.x4
    uint32_t afr[2][4][4];
#pragma unroll
    for (int mt = 0; mt < 2; mt++) {
        int rsh = wid * 32 + mt * 16 + (lane & 15);
#pragma unroll
        for (int kc = 0; kc < 4; kc++) {
            uint32_t addr = xs_u32 + rsh * (XS_STRIDE * 2) + kc * 32 + (lane >> 4) * 16;
            asm volatile("ldmatrix.sync.aligned.m8n8.x4.shared.b16 {%0,%1,%2,%3}, [%4];"
                         : "=r"(afr[mt][kc][0]), "=r"(afr[mt][kc][1]),
                           "=r"(afr[mt][kc][2]), "=r"(afr[mt][kc][3])
                         : "r"(addr));
        }
    }

    float c[8][2][4];                            // [ntile][mtile][c0..c3]
#pragma unroll
    for (int nt = 0; nt < 8; nt++)
#pragma unroll
        for (int mt = 0; mt < 2; mt++)
#pragma unroll
            for (int q = 0; q < 4; q++) c[nt][mt][q] = 0.f;

#pragma unroll
    for (int nt = 0; nt < 8; nt++) {
        // B fragments: b0 = wt[n][kc*16+2t .. +1], b1 = +8 halves (LDS.32 each)
        uint32_t b0[4], b1[4];
        int nrow = nt * 8 + g;
#pragma unroll
        for (int kc = 0; kc < 4; kc++) {
            b0[kc] = *reinterpret_cast<const uint32_t*>(&wt[nrow * XS_STRIDE + kc * 16 + 2 * t]);
            b1[kc] = *reinterpret_cast<const uint32_t*>(&wt[nrow * XS_STRIDE + kc * 16 + 8 + 2 * t]);
        }
#pragma unroll
        for (int mt = 0; mt < 2; mt++) {
#pragma unroll
            for (int kc = 0; kc < 4; kc++) {
                asm volatile(
                    "mma.sync.aligned.m16n8k16.row.col.f32.f16.f16.f32 "
                    "{%0,%1,%2,%3}, {%4,%5,%6,%7}, {%8,%9}, {%0,%1,%2,%3};"
                    : "+f"(c[nt][mt][0]), "+f"(c[nt][mt][1]),
                      "+f"(c[nt][mt][2]), "+f"(c[nt][mt][3])
                    : "r"(afr[mt][kc][0]), "r"(afr[mt][kc][1]),
                      "r"(afr[mt][kc][2]), "r"(afr[mt][kc][3]),
                      "r"(b0[kc]), "r"(b1[kc]));
            }
        }
    }

    // ---- epilogue: scale by rsqrt(deg+1), pack fp16, store ----
    __half* hnh = reinterpret_cast<__half*>(g_hn);
    int blockRow = blockIdx.x * 256 + wid * 32;
#pragma unroll
    for (int mt = 0; mt < 2; mt++) {
        int r0 = blockRow + mt * 16 + g;
        int r1 = r0 + 8;
        float di0 = (r0 < n) ? rsqrtf((float)(g_cnt[r0] + 1)) : 0.f;
        float di1 = (r1 < n) ? rsqrtf((float)(g_cnt[r1] + 1)) : 0.f;
#pragma unroll
        for (int nt = 0; nt < 8; nt++) {
            int col = nt * 8 + 2 * t;
            if (r0 < n) {
                __half2 h = __floats2half2_rn(c[nt][mt][0] * di0, c[nt][mt][1] * di0);
                *reinterpret_cast<__half2*>(&hnh[(size_t)r0 * DD + col]) = h;
            }
            if (r1 < n) {
                __half2 h = __floats2half2_rn(c[nt][mt][2] * di1, c[nt][mt][3] * di1);
                *reinterpret_cast<__half2*>(&hnh[(size_t)r1 * DD + col]) = h;
            }
        }
    }
}

// ---- aggregation: out = relu(dinv[i]*(hn[i] + sum_nbr hn[s]) + b) ----
// 8 lanes/node (4 nodes/warp), uint4 row gathers, bucket indices as int4.
// layer==1 zeroes g_cnt[node] after last read (replay invariant).
__global__ void __launch_bounds__(256) k_agg(
    const float* __restrict__ b, float* __restrict__ dout,
    int layer, int n) {
    int tid = blockIdx.x * blockDim.x + threadIdx.x;
    int node = tid >> 3;
    int sub = tid & 7;                 // owns half2[4*sub .. 4*sub+3]
    if (node >= n) return;
    float* out = (layer == 0) ? g_h1 : dout;
    const uint4* hn4 = reinterpret_cast<const uint4*>(g_hn);

    int cnt = g_cnt[node];
    float di = rsqrtf((float)(cnt + 1));
    int len = min(cnt, CAP);
    const int4* bp = reinterpret_cast<const int4*>(g_bkt + (size_t)node * CAP);

    uint4 uself = hn4[(size_t)node * 8 + sub];
    float2 a0 = __half22float2(*reinterpret_cast<__half2*>(&uself.x));
    float2 a1 = __half22float2(*reinterpret_cast<__half2*>(&uself.y));
    float2 a2 = __half22float2(*reinterpret_cast<__half2*>(&uself.z));
    float2 a3 = __half22float2(*reinterpret_cast<__half2*>(&uself.w));
    float2 c0 = {0.f, 0.f}, c1 = {0.f, 0.f}, c2 = {0.f, 0.f}, c3 = {0.f, 0.f};

#define ACC_U4(U, X0, X1, X2, X3)                                         \
    {                                                                     \
        float2 f0 = __half22float2(*reinterpret_cast<__half2*>(&(U).x));  \
        float2 f1 = __half22float2(*reinterpret_cast<__half2*>(&(U).y));  \
        float2 f2 = __half22float2(*reinterpret_cast<__half2*>(&(U).z));  \
        float2 f3 = __half22float2(*reinterpret_cast<__half2*>(&(U).w));  \
        X0.x += f0.x; X0.y += f0.y; X1.x += f1.x; X1.y += f1.y;           \
        X2.x += f2.x; X2.y += f2.y; X3.x += f3.x; X3.y += f3.y;           \
    }

    int p = 0;
    for (; p + 4 <= len; p += 4) {
        int4 e = bp[p >> 2];                      // broadcast across 8 lanes
        uint4 u0 = hn4[(size_t)e.x * 8 + sub];
        uint4 u1 = hn4[(size_t)e.y * 8 + sub];
        uint4 u2 = hn4[(size_t)e.z * 8 + sub];
        uint4 u3 = hn4[(size_t)e.w * 8 + sub];
        ACC_U4(u0, a0, a1, a2, a3)
        ACC_U4(u1, c0, c1, c2, c3)
        ACC_U4(u2, a0, a1, a2, a3)
        ACC_U4(u3, c0, c1, c2, c3)
    }
    for (; p < len; p++) {
        int s = g_bkt[(size_t)node * CAP + p];
        uint4 u0 = hn4[(size_t)s * 8 + sub];
        ACC_U4(u0, a0, a1, a2, a3)
    }
#undef ACC_U4

    if (layer == 1 && sub == 0) g_cnt[node] = 0;   // clean for next replay

    const float4* b4 = reinterpret_cast<const float4*>(b);
    float4 bA = b4[sub * 2], bB = b4[sub * 2 + 1];
    float4 oA, oB;
    oA.x = fmaxf((a0.x + c0.x) * di + bA.x, 0.f);
    oA.y = fmaxf((a0.y + c0.y) * di + bA.y, 0.f);
    oA.z = fmaxf((a1.x + c1.x) * di + bA.z, 0.f);
    oA.w = fmaxf((a1.y + c1.y) * di + bA.w, 0.f);
    oB.x = fmaxf((a2.x + c2.x) * di + bB.x, 0.f);
    oB.y = fmaxf((a2.y + c2.y) * di + bB.y, 0.f);
    oB.z = fmaxf((a3.x + c3.x) * di + bB.z, 0.f);
    oB.w = fmaxf((a3.y + c3.y) * di + bB.w, 0.f);
    float4* op = reinterpret_cast<float4*>(out + (size_t)node * DD + sub * 8);
    op[0] = oA;
    op[1] = oB;
}

// ---------------- launch (ONLY kernel launches — nothing else) ----------------
extern "C" void kernel_launch(void* const* d_in, const int* in_sizes, int n_in,
                              void* d_out, int out_size) {
    const float* emb = (const float*)d_in[0];
    const int*   ei  = (const int*)d_in[1];     // int32 (JAX x64 disabled)
    const float* W1  = (const float*)d_in[2];
    const float* b1  = (const float*)d_in[3];
    const float* W2  = (const float*)d_in[4];
    const float* b2  = (const float*)d_in[5];
    float*       out = (float*)d_out;

    int N = in_sizes[0] / DD;
    int E = in_sizes[1] / 2;
    const int* srcp = ei;       // edge_index[0]
    const int* dstp = ei + E;   // edge_index[1]
    int e2 = E / 2;             // 2 edges per thread

    // single-pass preprocessing: bucket CSR + degree counts (1 launch)
    k_scatter<<<(e2 + 255) / 256, 256>>>(srcp, dstp, e2, N);

    // layer 1
    k_gemm<<<(N + 255) / 256, 256>>>(emb, W1, 0, N);
    k_agg<<<(N * 8 + 255) / 256, 256>>>(b1, out, 0, N);
    // layer 2  (launch #4 -> profiled next round)
    k_gemm<<<(N + 255) / 256, 256>>>(emb, W2, 1, N);
    k_agg<<<(N * 8 + 255) / 256, 256>>>(b2, out, 1, N);
}

// round 10
// speedup vs baseline: 2.6631x; 1.0368x over previous
#include <cuda_runtime.h>
#include <cuda_fp16.h>
#include <cstdint>

// Problem constants (fixed by the dataset)
#define NN 100000
#define NE 1600000
#define DD 64
#define CAP 64          // bucket capacity per node (Poisson(16): P(deg>64)~2e-22)

#define XS_STRIDE 72    // halves; 144B rows: 16B-aligned + conflict-free ldmatrix

// ---------------- device scratch (no allocations allowed) ----------------
// g_cnt relies on BSS zero-init; agg layer-2 re-zeroes it (replay invariant).
__device__ __align__(256) int     g_cnt[NN];
__device__ __align__(256) float   g_dinv[NN];
__device__ __align__(256) int     g_bkt[(size_t)NN * CAP];   // bucket CSR
__device__ __align__(256) __half2 g_hn[(size_t)NN * 32];     // x@W (UNSCALED), fp16
__device__ __align__(256) __half  g_h1h[(size_t)NN * DD];    // layer-1 out, fp16

// -------- GEMM (+ fused edge scatter on layer 0): g_hn[row] = fp16(x@W) -----
// Block = 256 threads/8 warps/256 rows. mma.sync.m16n8k16 f32.f16.f16.f32.
// Scatter atomics (L2 pipe) overlap the latency-bound mma work for free.
// Epilogue: frags -> shared -> fully coalesced STG.128.
__global__ void __launch_bounds__(256) k_gemm(
    const float* __restrict__ emb, const float* __restrict__ W,
    const int* __restrict__ src, const int* __restrict__ dst,
    int e2, int layer, int n) {
    __shared__ __half xs[256 * XS_STRIDE];       // 36864 B
    __shared__ __half wt[64 * XS_STRIDE];        //  9216 B  (wt[n][k])
    int tid = threadIdx.x;
    int base = blockIdx.x * 256;

    // ---- stage x rows -> fp16 shared ----
    if (layer == 0) {
        int row = base + tid;
        const float4* xr = reinterpret_cast<const float4*>(emb + (size_t)row * DD);
        bool v = row < n;
        __half2* dstp = reinterpret_cast<__half2*>(&xs[tid * XS_STRIDE]);
#pragma unroll
        for (int kk = 0; kk < 16; kk++) {
            float4 q = v ? xr[kk] : make_float4(0.f, 0.f, 0.f, 0.f);
            dstp[kk * 2]     = __floats2half2_rn(q.x, q.y);
            dstp[kk * 2 + 1] = __floats2half2_rn(q.z, q.w);
        }
    } else {
        const uint4* inp = reinterpret_cast<const uint4*>(g_h1h);
        uint4 z = make_uint4(0, 0, 0, 0);
#pragma unroll
        for (int ii = 0; ii < 8; ii++) {
            int i = tid + 256 * ii;
            int r = i >> 3, pc = i & 7;
            int gr = base + r;
            uint4 v = (gr < n) ? inp[(size_t)gr * 8 + pc] : z;
            reinterpret_cast<uint4*>(&xs[r * XS_STRIDE])[pc] = v;
        }
    }
    // ---- stage W -> fp16 transposed shared (wt[n][k]) ----
    {
        const float4* Wp4 = reinterpret_cast<const float4*>(W);
#pragma unroll
        for (int ii = 0; ii < 4; ii++) {
            int i4 = tid + 256 * ii;             // 1024 float4 total
            float4 wv = Wp4[i4];
            int flat = i4 * 4;
            int k = flat >> 6;
            int nn = flat & 63;
            wt[(nn)     * XS_STRIDE + k] = __float2half_rn(wv.x);
            wt[(nn + 1) * XS_STRIDE + k] = __float2half_rn(wv.y);
            wt[(nn + 2) * XS_STRIDE + k] = __float2half_rn(wv.z);
            wt[(nn + 3) * XS_STRIDE + k] = __float2half_rn(wv.w);
        }
    }

    // ---- fused bucket scatter (layer 0 only; e2 = E/2 int2 pairs) ----
    int nthreads = gridDim.x * 256;
    for (int i = base + tid; i < e2; i += nthreads) {
        int2 s2 = reinterpret_cast<const int2*>(src)[i];
        int2 d2 = reinterpret_cast<const int2*>(dst)[i];
#pragma unroll
        for (int q = 0; q < 2; q++) {
            int d = q ? d2.y : d2.x;
            int s = q ? s2.y : s2.x;
            if ((unsigned)d >= (unsigned)n || (unsigned)s >= (unsigned)n) continue;
            int slot = atomicAdd(&g_cnt[d], 1);
            if (slot < CAP) g_bkt[(size_t)d * CAP + slot] = s;
        }
    }
    __syncthreads();

    int wid = tid >> 5, lane = tid & 31;
    int g = lane >> 2, t = lane & 3;
    uint32_t xs_u32 = (uint32_t)__cvta_generic_to_shared(xs);

    // A fragments via ldmatrix.x4
    uint32_t afr[2][4][4];
#pragma unroll
    for (int mt = 0; mt < 2; mt++) {
        int rsh = wid * 32 + mt * 16 + (lane & 15);
#pragma unroll
        for (int kc = 0; kc < 4; kc++) {
            uint32_t addr = xs_u32 + rsh * (XS_STRIDE * 2) + kc * 32 + (lane >> 4) * 16;
            asm volatile("ldmatrix.sync.aligned.m8n8.x4.shared.b16 {%0,%1,%2,%3}, [%4];"
                         : "=r"(afr[mt][kc][0]), "=r"(afr[mt][kc][1]),
                           "=r"(afr[mt][kc][2]), "=r"(afr[mt][kc][3])
                         : "r"(addr));
        }
    }

    float c[8][2][4];
#pragma unroll
    for (int nt = 0; nt < 8; nt++)
#pragma unroll
        for (int mt = 0; mt < 2; mt++)
#pragma unroll
            for (int q = 0; q < 4; q++) c[nt][mt][q] = 0.f;

#pragma unroll
    for (int nt = 0; nt < 8; nt++) {
        uint32_t b0[4], b1[4];
        int nrow = nt * 8 + g;
#pragma unroll
        for (int kc = 0; kc < 4; kc++) {
            b0[kc] = *reinterpret_cast<const uint32_t*>(&wt[nrow * XS_STRIDE + kc * 16 + 2 * t]);
            b1[kc] = *reinterpret_cast<const uint32_t*>(&wt[nrow * XS_STRIDE + kc * 16 + 8 + 2 * t]);
        }
#pragma unroll
        for (int mt = 0; mt < 2; mt++) {
#pragma unroll
            for (int kc = 0; kc < 4; kc++) {
                asm volatile(
                    "mma.sync.aligned.m16n8k16.row.col.f32.f16.f16.f32 "
                    "{%0,%1,%2,%3}, {%4,%5,%6,%7}, {%8,%9}, {%0,%1,%2,%3};"
                    : "+f"(c[nt][mt][0]), "+f"(c[nt][mt][1]),
                      "+f"(c[nt][mt][2]), "+f"(c[nt][mt][3])
                    : "r"(afr[mt][kc][0]), "r"(afr[mt][kc][1]),
                      "r"(afr[mt][kc][2]), "r"(afr[mt][kc][3]),
                      "r"(b0[kc]), "r"(b1[kc]));
            }
        }
    }
    __syncthreads();   // xs reuse

    // ---- epilogue: frags -> shared (conflict-free) ----
#pragma unroll
    for (int mt = 0; mt < 2; mt++) {
        int rl = wid * 32 + mt * 16 + g;
#pragma unroll
        for (int nt = 0; nt < 8; nt++) {
            int col = nt * 8 + 2 * t;
            *reinterpret_cast<__half2*>(&xs[rl * XS_STRIDE + col]) =
                __floats2half2_rn(c[nt][mt][0], c[nt][mt][1]);
            *reinterpret_cast<__half2*>(&xs[(rl + 8) * XS_STRIDE + col]) =
                __floats2half2_rn(c[nt][mt][2], c[nt][mt][3]);
        }
    }
    __syncthreads();

    // ---- shared -> global, fully coalesced STG.128 ----
    uint4* outp = reinterpret_cast<uint4*>(g_hn) + (size_t)base * 8;
    int limit = (min(256, n - base)) * 8;
#pragma unroll
    for (int ii = 0; ii < 8; ii++) {
        int i = tid + 256 * ii;
        if (i < limit) {
            int r = i >> 3, pc = i & 7;
            outp[i] = reinterpret_cast<uint4*>(&xs[r * XS_STRIDE])[pc];
        }
    }
}

// ---- dinv materialization: g_dinv = rsqrt(cnt+1)  (cnt zeroed later by agg2)
__global__ void k_dinv(int n) {
    int i = blockIdx.x * blockDim.x + threadIdx.x;
    if (i < n) g_dinv[i] = rsqrtf((float)(g_cnt[i] + 1));
}

// ---- aggregation: out = relu(dinv_d*(dinv_d*hn_d + sum_s dinv_s*hn_s) + b) --
// 8 lanes/node (4 nodes/warp), uint4 row gathers, per-edge dinv broadcast
// loads, fp32 fma accumulate. layer 0 -> fp16 g_h1h; layer 1 -> fp32 d_out
// (and zeroes g_cnt[node] — safe: no other block reads cnt anymore).
__global__ void __launch_bounds__(256) k_agg(
    const float* __restrict__ b, float* __restrict__ dout,
    int layer, int n) {
    int tid = blockIdx.x * blockDim.x + threadIdx.x;
    int node = tid >> 3;
    int sub = tid & 7;                 // owns half2[4*sub .. 4*sub+3]
    if (node >= n) return;
    const uint4* hn4 = reinterpret_cast<const uint4*>(g_hn);

    int cnt = g_cnt[node];
    float di = g_dinv[node];
    int len = min(cnt, CAP);
    const int4* bp = reinterpret_cast<const int4*>(g_bkt + (size_t)node * CAP);

    uint4 uself = hn4[(size_t)node * 8 + sub];
    float2 f0 = __half22float2(*reinterpret_cast<__half2*>(&uself.x));
    float2 f1 = __half22float2(*reinterpret_cast<__half2*>(&uself.y));
    float2 f2 = __half22float2(*reinterpret_cast<__half2*>(&uself.z));
    float2 f3 = __half22float2(*reinterpret_cast<__half2*>(&uself.w));
    float2 a0 = {f0.x * di, f0.y * di}, a1 = {f1.x * di, f1.y * di};
    float2 a2 = {f2.x * di, f2.y * di}, a3 = {f3.x * di, f3.y * di};
    float2 c0 = {0.f, 0.f}, c1 = {0.f, 0.f}, c2 = {0.f, 0.f}, c3 = {0.f, 0.f};

#define ACCS(U, DS, X0, X1, X2, X3)                                       \
    {                                                                     \
        float2 h0 = __half22float2(*reinterpret_cast<__half2*>(&(U).x));  \
        float2 h1 = __half22float2(*reinterpret_cast<__half2*>(&(U).y));  \
        float2 h2 = __half22float2(*reinterpret_cast<__half2*>(&(U).z));  \
        float2 h3 = __half22float2(*reinterpret_cast<__half2*>(&(U).w));  \
        X0.x = fmaf(h0.x, DS, X0.x); X0.y = fmaf(h0.y, DS, X0.y);         \
        X1.x = fmaf(h1.x, DS, X1.x); X1.y = fmaf(h1.y, DS, X1.y);         \
        X2.x = fmaf(h2.x, DS, X2.x); X2.y = fmaf(h2.y, DS, X2.y);         \
        X3.x = fmaf(h3.x, DS, X3.x); X3.y = fmaf(h3.y, DS, X3.y);         \
    }

    int p = 0;
    for (; p + 4 <= len; p += 4) {
        int4 e = bp[p >> 2];                      // broadcast across 8 lanes
        float d0 = g_dinv[e.x], d1 = g_dinv[e.y];
        float d2v = g_dinv[e.z], d3v = g_dinv[e.w];
        uint4 u0 = hn4[(size_t)e.x * 8 + sub];
        uint4 u1 = hn4[(size_t)e.y * 8 + sub];
        uint4 u2 = hn4[(size_t)e.z * 8 + sub];
        uint4 u3 = hn4[(size_t)e.w * 8 + sub];
        ACCS(u0, d0, a0, a1, a2, a3)
        ACCS(u1, d1, c0, c1, c2, c3)
        ACCS(u2, d2v, a0, a1, a2, a3)
        ACCS(u3, d3v, c0, c1, c2, c3)
    }
    for (; p < len; p++) {
        int s = g_bkt[(size_t)node * CAP + p];
        float ds = g_dinv[s];
        uint4 u0 = hn4[(size_t)s * 8 + sub];
        ACCS(u0, ds, a0, a1, a2, a3)
    }
#undef ACCS

    if (layer == 1 && sub == 0) g_cnt[node] = 0;   // clean for next replay

    const float4* b4 = reinterpret_cast<const float4*>(b);
    float4 bA = b4[sub * 2], bB = b4[sub * 2 + 1];
    float vA0 = fmaxf((a0.x + c0.x) * di + bA.x, 0.f);
    float vA1 = fmaxf((a0.y + c0.y) * di + bA.y, 0.f);
    float vA2 = fmaxf((a1.x + c1.x) * di + bA.z, 0.f);
    float vA3 = fmaxf((a1.y + c1.y) * di + bA.w, 0.f);
    float vB0 = fmaxf((a2.x + c2.x) * di + bB.x, 0.f);
    float vB1 = fmaxf((a2.y + c2.y) * di + bB.y, 0.f);
    float vB2 = fmaxf((a3.x + c3.x) * di + bB.z, 0.f);
    float vB3 = fmaxf((a3.y + c3.y) * di + bB.w, 0.f);

    if (layer == 0) {
        // pack to fp16 h1 (gemm2 input): one uint4 store
        __half2 h0 = __floats2half2_rn(vA0, vA1);
        __half2 h1 = __floats2half2_rn(vA2, vA3);
        __half2 h2 = __floats2half2_rn(vB0, vB1);
        __half2 h3 = __floats2half2_rn(vB2, vB3);
        uint4 pk;
        pk.x = *reinterpret_cast<unsigned*>(&h0);
        pk.y = *reinterpret_cast<unsigned*>(&h1);
        pk.z = *reinterpret_cast<unsigned*>(&h2);
        pk.w = *reinterpret_cast<unsigned*>(&h3);
        reinterpret_cast<uint4*>(g_h1h + (size_t)node * DD)[sub] = pk;
    } else {
        float4* op = reinterpret_cast<float4*>(dout + (size_t)node * DD + sub * 8);
        op[0] = make_float4(vA0, vA1, vA2, vA3);
        op[1] = make_float4(vB0, vB1, vB2, vB3);
    }
}

// ---------------- launch (ONLY kernel launches — nothing else) ----------------
extern "C" void kernel_launch(void* const* d_in, const int* in_sizes, int n_in,
                              void* d_out, int out_size) {
    const float* emb = (const float*)d_in[0];
    const int*   ei  = (const int*)d_in[1];     // int32 (JAX x64 disabled)
    const float* W1  = (const float*)d_in[2];
    const float* b1  = (const float*)d_in[3];
    const float* W2  = (const float*)d_in[4];
    const float* b2  = (const float*)d_in[5];
    float*       out = (float*)d_out;

    int N = in_sizes[0] / DD;
    int E = in_sizes[1] / 2;
    const int* srcp = ei;       // edge_index[0]
    const int* dstp = ei + E;   // edge_index[1]
    int e2 = E / 2;             // int2 pairs
    int gblocks = (N + 255) / 256;

    // layer 1 GEMM with fused edge scatter
    k_gemm<<<gblocks, 256>>>(emb, W1, srcp, dstp, e2, 0, N);
    k_dinv<<<(N + 255) / 256, 256>>>(N);
    k_agg<<<(N * 8 + 255) / 256, 256>>>(b1, out, 0, N);
    // layer 2  (launch #4 -> profiled next round)
    k_gemm<<<gblocks, 256>>>(emb, W2, srcp, dstp, 0, 1, N);
    k_agg<<<(N * 8 + 255) / 256, 256>>>(b2, out, 1, N);
}